// round 5
// baseline (speedup 1.0000x reference)
#include <cuda_runtime.h>
#include <math.h>
#include <stdint.h>

#define BB 8
#define TT 2048
#define CC 1024
#define HH 128

__device__ float g_q[BB * TT * HH];
__device__ float g_k[BB * TT * HH];
__device__ float g_v[BB * TT * HH];

// ---------------------------------------------------------------------------
// PTX helpers
// ---------------------------------------------------------------------------
__device__ __forceinline__ void mma_tf32(float c[4], const uint32_t a[4],
                                         uint32_t b0, uint32_t b1) {
    asm volatile(
        "mma.sync.aligned.m16n8k8.row.col.f32.tf32.tf32.f32 "
        "{%0,%1,%2,%3}, {%4,%5,%6,%7}, {%8,%9}, {%0,%1,%2,%3};"
        : "+f"(c[0]), "+f"(c[1]), "+f"(c[2]), "+f"(c[3])
        : "r"(a[0]), "r"(a[1]), "r"(a[2]), "r"(a[3]), "r"(b0), "r"(b1));
}

__device__ __forceinline__ void ldsm_x4(uint32_t r[4], uint32_t addr) {
    asm volatile("ldmatrix.sync.aligned.m8n8.x4.shared.b16 {%0,%1,%2,%3}, [%4];"
        : "=r"(r[0]), "=r"(r[1]), "=r"(r[2]), "=r"(r[3]) : "r"(addr));
}

__device__ __forceinline__ uint32_t f2tf(float f) {
    uint32_t u;
    asm("cvt.rna.tf32.f32 %0, %1;" : "=r"(u) : "f"(f));
    return u;
}
__device__ __forceinline__ float f2tff(float f) { return __uint_as_float(f2tf(f)); }

__device__ __forceinline__ uint32_t smem_u32(const void* p) {
    uint32_t a;
    asm("{ .reg .u64 t; cvta.to.shared.u64 t, %1; cvt.u32.u64 %0, t; }" : "=r"(a) : "l"(p));
    return a;
}

#define CP_ASYNC16(dst, src) \
    asm volatile("cp.async.cg.shared.global [%0], [%1], 16;" :: "r"(dst), "l"(src) : "memory")
#define CP_COMMIT() asm volatile("cp.async.commit_group;" ::: "memory")
#define CP_WAIT0()  asm volatile("cp.async.wait_group 0;" ::: "memory")
#define CP_WAIT1()  asm volatile("cp.async.wait_group 1;" ::: "memory")
#define CP_WAIT2()  asm volatile("cp.async.wait_group 2;" ::: "memory")

// ===========================================================================
// Kernel 1: QKV projection, tf32 mma.sync + ldmatrix.
// out[r][h] = sum_c x[r][c] * W[h][c].  M=16384, N=128, K=1024.
// BM=128, BN=128, BK=32. 256 threads = 8 warps (4 M x 2 N), warp tile 32x64.
// Smem: As[128][36], Bs[128][36], double buffered (73.7 KB).
// ===========================================================================
#define QKV_AS 4608              // 128*36 floats
#define QKV_SMEM_BYTES (4 * QKV_AS * 4)

__global__ __launch_bounds__(256, 1) void qkv_mma_kernel(
    const float* __restrict__ x,
    const float* __restrict__ Wq,
    const float* __restrict__ Wk,
    const float* __restrict__ Wv)
{
    extern __shared__ float sm[];
    const uint32_t sb = smem_u32(sm);
    const int mat = blockIdx.y;
    const float* W = (mat == 0) ? Wq : (mat == 1) ? Wk : Wv;
    float* out = (mat == 0) ? g_q : (mat == 1) ? g_k : g_v;

    const int tid = threadIdx.x;
    const int lid = tid & 31;
    const int wid = tid >> 5;
    const int g = lid >> 2;
    const int c = lid & 3;
    const int wm = wid & 3;       // M group (32 rows)
    const int wn = wid >> 2;      // N group (64 cols)
    const int m0 = blockIdx.x * 128;

    // ldmatrix lane offsets (bytes); row stride = 36 floats = 144 B (16B-aligned)
    const uint32_t a_l_off = ((((lid >> 3) & 1) * 8 + (lid & 7)) * 144) + ((lid >> 4) * 16);
    const uint32_t b_l_off = ((lid & 7) * 144) + ((lid >> 3) * 16);

    float acc[2][8][4];
    #pragma unroll
    for (int mi = 0; mi < 2; mi++)
        #pragma unroll
        for (int ni = 0; ni < 8; ni++)
            #pragma unroll
            for (int j = 0; j < 4; j++) acc[mi][ni][j] = 0.0f;

    float4 xr[4], wr[4];

    auto loadT = [&](int it) {
        const int k0 = it * 32;
        #pragma unroll
        for (int j = 0; j < 4; j++) {
            int idx = tid + j * 256;
            int m = idx >> 3;
            int kq = (idx & 7) << 2;
            xr[j] = *reinterpret_cast<const float4*>(&x[(size_t)(m0 + m) * CC + k0 + kq]);
            wr[j] = *reinterpret_cast<const float4*>(&W[(size_t)m * CC + k0 + kq]);
        }
    };
    auto stsT = [&](int p) {
        float* As = sm + p * QKV_AS;
        float* Bs = sm + 2 * QKV_AS + p * QKV_AS;
        #pragma unroll
        for (int j = 0; j < 4; j++) {
            int idx = tid + j * 256;
            int m = idx >> 3;
            int kq = (idx & 7) << 2;
            uint4 ua = make_uint4(f2tf(xr[j].x), f2tf(xr[j].y), f2tf(xr[j].z), f2tf(xr[j].w));
            uint4 ub = make_uint4(f2tf(wr[j].x), f2tf(wr[j].y), f2tf(wr[j].z), f2tf(wr[j].w));
            *reinterpret_cast<uint4*>(&As[m * 36 + kq]) = ua;
            *reinterpret_cast<uint4*>(&Bs[m * 36 + kq]) = ub;
        }
    };

    loadT(0);
    stsT(0);
    __syncthreads();

    for (int it = 0; it < 32; ++it) {
        const int p = it & 1;
        if (it < 31) loadT(it + 1);

        const uint32_t aaddr0 = sb + p * (QKV_AS * 4) + wm * (32 * 144) + a_l_off;
        const uint32_t aaddr1 = aaddr0 + 16 * 144;
        const uint32_t baddr  = sb + (2 + p) * (QKV_AS * 4) + wn * (64 * 144) + b_l_off;

        #pragma unroll
        for (int kp = 0; kp < 2; kp++) {
            uint32_t a0[4], a1[4], a0b[4], a1b[4];
            ldsm_x4(a0,  aaddr0 + kp * 64);        // ks = 2kp
            ldsm_x4(a1,  aaddr1 + kp * 64);
            ldsm_x4(a0b, aaddr0 + kp * 64 + 32);   // ks = 2kp+1
            ldsm_x4(a1b, aaddr1 + kp * 64 + 32);
            #pragma unroll
            for (int ni = 0; ni < 8; ni++) {
                uint32_t b4[4];
                ldsm_x4(b4, baddr + ni * (8 * 144) + kp * 64);
                mma_tf32(acc[0][ni], a0,  b4[0], b4[1]);
                mma_tf32(acc[1][ni], a1,  b4[0], b4[1]);
                mma_tf32(acc[0][ni], a0b, b4[2], b4[3]);
                mma_tf32(acc[1][ni], a1b, b4[2], b4[3]);
            }
        }

        if (it < 31) stsT(p ^ 1);
        __syncthreads();
    }

    // Epilogue: round to tf32 so attention operands are exact tf32.
    #pragma unroll
    for (int mi = 0; mi < 2; mi++) {
        int row0 = m0 + wm * 32 + mi * 16 + g;
        int row1 = row0 + 8;
        #pragma unroll
        for (int ni = 0; ni < 8; ni++) {
            int col = wn * 64 + ni * 8 + 2 * c;
            float2 v0 = make_float2(f2tff(acc[mi][ni][0]), f2tff(acc[mi][ni][1]));
            float2 v1 = make_float2(f2tff(acc[mi][ni][2]), f2tff(acc[mi][ni][3]));
            *reinterpret_cast<float2*>(&out[(size_t)row0 * HH + col]) = v0;
            *reinterpret_cast<float2*>(&out[(size_t)row1 * HH + col]) = v1;
        }
    }
}

// ===========================================================================
// Kernel 2: causal flash attention, tf32 mma.sync + ldmatrix, occupancy 2.
// BQ=BKV=64, 128 threads (4 warps), warp = 16 q-rows x 128 cols.
// Q frags loaded directly from gmem. K double-buffered (XOR-swizzled,
// stride 128). V single-buffered (XOR-swizzled), reload hidden under S-loop.
// P: stride 64 floats (256B rows, 16B-aligned) + XOR-chunk swizzle.
// Total smem 114,688 B -> 2 CTAs/SM.
// ===========================================================================
#define AK0 0            // K buf 0: 64 x 128 (swizzled), floats
#define AK1 8192
#define AV  16384        // V: 64 x 128 (swizzled)
#define AP  24576        // P: 64 x 64 (swizzled)
#define ATT_SMEM_FLOATS (24576 + 64 * 64)
#define ATT_SMEM_BYTES (ATT_SMEM_FLOATS * 4)   // 114,688

__global__ __launch_bounds__(128, 2) void attn_mma_kernel(float* __restrict__ out)
{
    extern __shared__ float sm[];
    uint32_t* su = reinterpret_cast<uint32_t*>(sm);
    const uint32_t sb = smem_u32(sm);

    const int b  = blockIdx.y;
    const int qt = (gridDim.x - 1) - blockIdx.x;   // heavy tiles first
    const int q0 = qt * 64;
    const int tid = threadIdx.x;
    const int wid = tid >> 5;
    const int lid = tid & 31;
    const int g = lid >> 2;
    const int c = lid & 3;
    const int r0w = wid * 16;

    const float* qg = g_q + (size_t)b * TT * HH;
    const float* kg = g_k + (size_t)b * TT * HH;
    const float* vg = g_v + (size_t)b * TT * HH;

    // K tile loader: rows r (kv), 16B chunk kc -> swizzled chunk kc ^ (r&7)
    auto cpa_k = [&](uint32_t kbytes, int kt) {
        const float* src = kg + (size_t)(kt * 64) * HH;
        #pragma unroll
        for (int i = 0; i < 16; i++) {
            int idx = tid + i * 128;
            int r = idx >> 5, kc = idx & 31;
            uint32_t dst = sb + kbytes + r * 512 + ((kc ^ (r & 7)) << 4);
            CP_ASYNC16(dst, src + (size_t)r * HH + kc * 4);
        }
    };
    // V tile loader: float-index swizzle f' = f ^ ((r&3)<<3)
    auto cpa_v = [&](int kt) {
        const float* src = vg + (size_t)(kt * 64) * HH;
        #pragma unroll
        for (int i = 0; i < 16; i++) {
            int idx = tid + i * 128;
            int r = idx >> 5, kc = idx & 31;
            uint32_t fs = (uint32_t)((kc << 2) ^ ((r & 3) << 3));
            uint32_t dst = sb + AV * 4 + r * 512 + (fs << 2);
            CP_ASYNC16(dst, src + (size_t)r * HH + kc * 4);
        }
    };

    // Prologue: K[0] (group), V[0] (group)
    cpa_k(AK0 * 4, 0);
    CP_COMMIT();
    cpa_v(0);
    CP_COMMIT();

    // Q fragments straight from gmem (rows already tf32-rounded by kernel 1)
    uint32_t qa[16][4];
    {
        const float* qrow0 = qg + (size_t)(q0 + r0w + g) * HH;
        const float* qrow1 = qrow0 + 8 * HH;
        #pragma unroll
        for (int ks = 0; ks < 16; ks++) {
            qa[ks][0] = __float_as_uint(__ldg(&qrow0[ks * 8 + c]));
            qa[ks][1] = __float_as_uint(__ldg(&qrow1[ks * 8 + c]));
            qa[ks][2] = __float_as_uint(__ldg(&qrow0[ks * 8 + c + 4]));
            qa[ks][3] = __float_as_uint(__ldg(&qrow1[ks * 8 + c + 4]));
        }
    }

    // ldmatrix lane constants
    const uint32_t rl = lid & 7;          // K-frag row-in-matrix / XOR key
    const uint32_t kq = lid >> 3;         // K-frag chunk select (0..3)
    const uint32_t krow_b = rl * 512;
    // P ldmatrix: lane -> row r0w + ((lid>>3)&1)*8 + rl, chunk parity (lid>>4)
    const uint32_t p_hi = (lid >> 4);
    const uint32_t prow = (uint32_t)r0w + (((lid >> 3) & 1) << 3) + rl;
    const uint32_t p_base = sb + AP * 4 + prow * 256;

    float o[16][4];
    #pragma unroll
    for (int nt = 0; nt < 16; nt++)
        #pragma unroll
        for (int j = 0; j < 4; j++) o[nt][j] = 0.0f;
    float m0s = -1e30f, m1s = -1e30f, l0 = 0.0f, l1 = 0.0f;

    const float sc = 0.08838834764831845f;
    const int nkt = qt + 1;
    const int grow0 = q0 + r0w + g;
    const int grow1 = grow0 + 8;

    for (int kt = 0; kt < nkt; ++kt) {
        const int p = kt & 1;
        const uint32_t kbase = sb + (p ? AK1 : AK0) * 4;

        if (kt < qt) {                     // prefetch K[kt+1] into other buffer
            cpa_k((p ? AK0 : AK1) * 4, kt + 1);
            CP_COMMIT();
            CP_WAIT2();                    // K[kt] done (V[kt], K[kt+1] may fly)
        } else {
            CP_WAIT1();                    // K[kt] done (V[kt] may fly)
        }
        __syncthreads();

        // ---- S = Q K^T ----
        float sa[8][4];
        #pragma unroll
        for (int nt = 0; nt < 8; nt++)
            #pragma unroll
            for (int j = 0; j < 4; j++) sa[nt][j] = 0.0f;

        #pragma unroll
        for (int kp = 0; kp < 8; kp++) {
            const uint32_t kcsw = (((kp * 4 + kq) ^ rl) << 4);
            #pragma unroll
            for (int nt = 0; nt < 8; nt++) {
                uint32_t b4[4];
                ldsm_x4(b4, kbase + nt * 4096 + krow_b + kcsw);
                mma_tf32(sa[nt], qa[2 * kp],     b4[0], b4[1]);
                mma_tf32(sa[nt], qa[2 * kp + 1], b4[2], b4[3]);
            }
        }

        // scale + causal mask
        const int k0 = kt * 64;
        #pragma unroll
        for (int nt = 0; nt < 8; nt++)
            #pragma unroll
            for (int j = 0; j < 4; j++) sa[nt][j] *= sc;
        if (kt == qt) {
            #pragma unroll
            for (int nt = 0; nt < 8; nt++) {
                int colb = k0 + nt * 8 + 2 * c;
                if (colb     > grow0) sa[nt][0] = -1e30f;
                if (colb + 1 > grow0) sa[nt][1] = -1e30f;
                if (colb     > grow1) sa[nt][2] = -1e30f;
                if (colb + 1 > grow1) sa[nt][3] = -1e30f;
            }
        }

        // online softmax
        float mt0 = -1e30f, mt1 = -1e30f;
        #pragma unroll
        for (int nt = 0; nt < 8; nt++) {
            mt0 = fmaxf(mt0, fmaxf(sa[nt][0], sa[nt][1]));
            mt1 = fmaxf(mt1, fmaxf(sa[nt][2], sa[nt][3]));
        }
        mt0 = fmaxf(mt0, __shfl_xor_sync(0xffffffffu, mt0, 1));
        mt0 = fmaxf(mt0, __shfl_xor_sync(0xffffffffu, mt0, 2));
        mt1 = fmaxf(mt1, __shfl_xor_sync(0xffffffffu, mt1, 1));
        mt1 = fmaxf(mt1, __shfl_xor_sync(0xffffffffu, mt1, 2));

        const float mn0 = fmaxf(m0s, mt0);
        const float mn1 = fmaxf(m1s, mt1);
        const float al0 = __expf(m0s - mn0);
        const float al1 = __expf(m1s - mn1);
        m0s = mn0; m1s = mn1;

        float lt0 = 0.0f, lt1 = 0.0f;
        #pragma unroll
        for (int nt = 0; nt < 8; nt++) {
            sa[nt][0] = __expf(sa[nt][0] - mn0);
            sa[nt][1] = __expf(sa[nt][1] - mn0);
            sa[nt][2] = __expf(sa[nt][2] - mn1);
            sa[nt][3] = __expf(sa[nt][3] - mn1);
            lt0 += sa[nt][0] + sa[nt][1];
            lt1 += sa[nt][2] + sa[nt][3];
        }
        lt0 += __shfl_xor_sync(0xffffffffu, lt0, 1);
        lt0 += __shfl_xor_sync(0xffffffffu, lt0, 2);
        lt1 += __shfl_xor_sync(0xffffffffu, lt1, 1);
        lt1 += __shfl_xor_sync(0xffffffffu, lt1, 2);
        l0 = l0 * al0 + lt0;
        l1 = l1 * al1 + lt1;

        #pragma unroll
        for (int nt = 0; nt < 16; nt++) {
            o[nt][0] *= al0; o[nt][1] *= al0;
            o[nt][2] *= al1; o[nt][3] *= al1;
        }

        // wait for V[kt]
        if (kt < qt) CP_WAIT1(); else CP_WAIT0();
        __syncthreads();

        // P -> smem (tf32-rounded), warp-private rows, stride 64 + XOR swizzle.
        // float2 at logical col f = nt*8 + 2c: group = 2nt + (c>>1) -> ^= (row&7)=g,
        // within-group float offset = 2*(c&1).
        {
            const int pr0 = AP + (r0w + g) * 64;
            const int pr8 = AP + (r0w + g + 8) * 64;
            const int foff = 2 * (c & 1);
            #pragma unroll
            for (int nt = 0; nt < 8; nt++) {
                const int grp = ((2 * nt + (c >> 1)) ^ g) << 2;
                float2 v0 = make_float2(f2tff(sa[nt][0]), f2tff(sa[nt][1]));
                float2 v1 = make_float2(f2tff(sa[nt][2]), f2tff(sa[nt][3]));
                *reinterpret_cast<float2*>(&sm[pr0 + grp + foff]) = v0;
                *reinterpret_cast<float2*>(&sm[pr8 + grp + foff]) = v1;
            }
        }
        __syncwarp();

        // ---- O += P V ----
        #pragma unroll
        for (int ks2 = 0; ks2 < 8; ks2++) {
            uint32_t pa[4];
            ldsm_x4(pa, p_base + ((((uint32_t)(2 * ks2) + p_hi) ^ rl) << 4));
            const int vkb = AV + (ks2 * 8 + c) * 128;
            #pragma unroll
            for (int nt = 0; nt < 16; nt++) {
                const int col = (nt * 8 + g) ^ (c << 3);
                uint32_t vb0 = su[vkb + col];
                uint32_t vb1 = su[vkb + 512 + col];
                mma_tf32(o[nt], pa, vb0, vb1);
            }
        }
        __syncthreads();                   // all warps done with V[kt]

        if (kt < qt) {                     // reload V for next tile
            cpa_v(kt + 1);
            CP_COMMIT();
        }
    }

    // Epilogue
    const float inv0 = 1.0f / l0;
    const float inv1 = 1.0f / l1;
    #pragma unroll
    for (int nt = 0; nt < 16; nt++) {
        int col = nt * 8 + 2 * c;
        float2 v0 = make_float2(o[nt][0] * inv0, o[nt][1] * inv0);
        float2 v1 = make_float2(o[nt][2] * inv1, o[nt][3] * inv1);
        *reinterpret_cast<float2*>(&out[((size_t)b * TT + grow0) * HH + col]) = v0;
        *reinterpret_cast<float2*>(&out[((size_t)b * TT + grow1) * HH + col]) = v1;
    }
}

// ---------------------------------------------------------------------------
extern "C" void kernel_launch(void* const* d_in, const int* in_sizes, int n_in,
                              void* d_out, int out_size)
{
    const float* x  = (const float*)d_in[0];
    const float* Wq = (const float*)d_in[1];
    const float* Wk = (const float*)d_in[2];
    const float* Wv = (const float*)d_in[3];
    float* out = (float*)d_out;

    cudaFuncSetAttribute(qkv_mma_kernel, cudaFuncAttributeMaxDynamicSharedMemorySize,
                         QKV_SMEM_BYTES);
    cudaFuncSetAttribute(attn_mma_kernel, cudaFuncAttributeMaxDynamicSharedMemorySize,
                         ATT_SMEM_BYTES);

    dim3 g1((BB * TT) / 128, 3);
    qkv_mma_kernel<<<g1, 256, QKV_SMEM_BYTES>>>(x, Wq, Wk, Wv);

    dim3 g2(TT / 64, BB);
    attn_mma_kernel<<<g2, 128, ATT_SMEM_BYTES>>>(out);
}